// round 16
// baseline (speedup 1.0000x reference)
#include <cuda_runtime.h>
#include <cuda_fp16.h>
#include <cstdint>

// ---------------- PTX helpers (family-level: sm_80/sm_90 non-'a') ----------------

__device__ __forceinline__ uint32_t smem_u32(const void* p) {
    uint32_t a;
    asm("{ .reg .u64 t; cvta.to.shared.u64 t, %1; cvt.u32.u64 %0, t; }" : "=r"(a) : "l"(p));
    return a;
}

#define LDSM_X4(r0,r1,r2,r3,addr) \
    asm volatile("ldmatrix.sync.aligned.m8n8.x4.shared.b16 {%0,%1,%2,%3}, [%4];" \
        : "=r"(r0),"=r"(r1),"=r"(r2),"=r"(r3) : "r"(addr))
#define LDSM_X2(r0,r1,addr) \
    asm volatile("ldmatrix.sync.aligned.m8n8.x2.shared.b16 {%0,%1}, [%2];" \
        : "=r"(r0),"=r"(r1) : "r"(addr))

#define MMA_16816(c,a0,a1,a2,a3,b0,b1) \
    asm volatile("mma.sync.aligned.m16n8k16.row.col.f32.f16.f16.f32 " \
        "{%0,%1,%2,%3}, {%4,%5,%6,%7}, {%8,%9}, {%0,%1,%2,%3};" \
        : "+f"((c)[0]),"+f"((c)[1]),"+f"((c)[2]),"+f"((c)[3]) \
        : "r"(a0),"r"(a1),"r"(a2),"r"(a3),"r"(b0),"r"(b1))
#define MMA_16808(c,a0,a1,b0) \
    asm volatile("mma.sync.aligned.m16n8k8.row.col.f32.f16.f16.f32 " \
        "{%0,%1,%2,%3}, {%4,%5}, {%6}, {%0,%1,%2,%3};" \
        : "+f"((c)[0]),"+f"((c)[1]),"+f"((c)[2]),"+f"((c)[3]) \
        : "r"(a0),"r"(a1),"r"(b0))

// bulk copy (UBLKCP, validated on compute_103) + mbarrier
#define CP_BULK(dst,src,size,mbar) \
    asm volatile("cp.async.bulk.shared::cluster.global.mbarrier::complete_tx::bytes " \
        "[%0], [%1], %2, [%3];" :: "r"(dst),"l"(src),"r"(size),"r"(mbar) : "memory")
#define MBARRIER_INIT(mbar, cnt) \
    asm volatile("mbarrier.init.shared.b64 [%0], %1;" :: "r"((uint32_t)(mbar)), "r"((uint32_t)(cnt)) : "memory")
#define MBARRIER_EXPECT_TX(mbar, tx) \
    asm volatile("mbarrier.arrive.expect_tx.shared.b64 _, [%0], %1;" :: "r"((uint32_t)(mbar)), "r"((uint32_t)(tx)) : "memory")
#define FENCE_PROXY_ASYNC() asm volatile("fence.proxy.async.shared::cta;" ::: "memory")

#define MBARRIER_WAIT_PARITY(mbar_smem_addr, phase_parity) do { \
    uint32_t _mbar = (uint32_t)(mbar_smem_addr); \
    uint32_t _parity = (uint32_t)(phase_parity); \
    uint32_t _done; \
    asm volatile( \
        "{\n\t.reg .pred p;\n\t" \
        "mbarrier.try_wait.parity.acquire.cta.shared::cta.b64 p, [%1], %2;\n\t" \
        "selp.b32 %0, 1, 0, p;\n\t}" \
        : "=r"(_done) : "r"(_mbar), "r"(_parity) : "memory"); \
    if (!_done) { \
        asm volatile( \
            "{\n\t.reg .pred P1;\n\t" \
            "WAIT_LOOP_%=:\n\t" \
            "mbarrier.try_wait.parity.acquire.cta.shared::cta.b64 P1, [%0], %1, 0x989680;\n\t" \
            "@P1 bra.uni WAIT_DONE_%=;\n\t" \
            "bra.uni WAIT_LOOP_%=;\n\t" \
            "WAIT_DONE_%=:\n\t}" \
            :: "r"(_mbar), "r"(_parity) : "memory"); \
    } \
} while(0)

__device__ __forceinline__ uint32_t packh2(float a, float b) {
    return (uint32_t)__half_as_ushort(__float2half_rn(a)) |
           ((uint32_t)__half_as_ushort(__float2half_rn(b)) << 16);
}

// ---------------- problem constants ----------------

static constexpr int DIM   = 128;
static constexpr int NEXP  = 8;
static constexpr int NTOK  = 524288;
static constexpr int MAX_TILES = 4160;
static constexpr int NPOS  = MAX_TILES * 128;

// main-kernel smem layout (bytes) — per CTA (2 CTAs/SM)
static constexpr int OFF_A    = 0;        // 32768  (x f16 tile image, pre-swizzled)
static constexpr int OFF_REC  = 32768;    // 4096   (per-row records: gf16B, ga, gb, tok, pad)
static constexpr int OFF_W    = 36864;    // 65536  [nh][ea|eb] 4 x 16KB half-images
static constexpr int OFF_BG   = 102400;   // 2048   (b^T f16 [128][16B], all cols)
static constexpr int OFF_MBAR = 104448;   // 2 x 8  (abar, wbar)
static constexpr int SMEM_MAIN = 104464;  // ~102 KB -> 2 CTAs/SM

static constexpr uint32_t W_TX = 65536u;

// ---------------- device scratch (static: no allocations) ----------------

__device__ __align__(16) unsigned char g_Wh[NEXP * 32768];       // [e][nh 16KB x2] images
__device__ __align__(16) unsigned char g_xh[(size_t)NTOK * 256]; // x f16, token order, PRE-SWIZZLED by rank&7
__device__ __align__(16) uint4 g_rec[(size_t)NTOK * 2];          // [tok]: {gf(16B)},{ga,gb,tok,0}
__device__ __align__(16) uint4 g_recg[(size_t)NPOS * 2];         // records in grouped (padded) order
__device__ int    g_hist[64];
__device__ int    g_off[64];                 // padded group base (multiple of 128)
__device__ int    g_ntiles[1];
__device__ int4   g_tiles[MAX_TILES];        // (start=tile*128, count, e_a, e_b)
__device__ uint32_t g_pr[NTOK];              // pair<<24 | rank
__device__ __align__(16) int g_tok[NPOS];    // grouped token ids (padded slots unused)

// ---------------- kernel 1: W fp32 -> f16 half-expert tile images ----------------

__global__ void convert_w_kernel(const float* __restrict__ W) {
    if (blockIdx.x == 0 && threadIdx.x < 64) g_hist[threadIdx.x] = 0;
    const int i = blockIdx.x * blockDim.x + threadIdx.x;   // 16384 16B-chunks
    const int e   = i >> 11;
    const int f   = (i >> 4) & 127;       // output feature row
    const int c16 = i & 15;
    const float4* src = (const float4*)(W + ((size_t)e * 128 + f) * 128 + c16 * 8);
    float4 v0 = src[0], v1 = src[1];
    uint4 u = make_uint4(packh2(v0.x, v0.y), packh2(v0.z, v0.w),
                         packh2(v1.x, v1.y), packh2(v1.z, v1.w));
    *(uint4*)(g_Wh + e * 32768 + (f >> 6) * 16384 + (f & 63) * 256
              + ((c16 ^ (f & 7)) << 4)) = u;
}

// ---------------- kernel 2: routing (gating + top-2 + pre-swizzled x->f16 + records) ----------------

__global__ void __launch_bounds__(256, 2)
routing_kernel(const float* __restrict__ x,
               const float* __restrict__ gW,
               const float* __restrict__ gb)
{
    __shared__ float gws[NEXP * DIM];
    __shared__ float part[256 * NEXP];
    __shared__ int   skey[128];

    const int tid  = threadIdx.x;
    const int row  = tid & 127;
    const int half = tid >> 7;
    const long tok0 = (long)blockIdx.x * 128;

    ((float4*)gws)[tid] = ((const float4*)gW)[tid];

    float4 xv[16];
    {
        const float4* xg = (const float4*)(x + (tok0 + row) * DIM + half * 64);
        #pragma unroll
        for (int i = 0; i < 16; i++) xv[i] = __ldg(xg + i);
    }
    __syncthreads();

    #pragma unroll
    for (int e = 0; e < NEXP; e++) {
        const float4* ge = (const float4*)(gws + e * DIM) + half * 16;
        float s = 0.f;
        #pragma unroll
        for (int i = 0; i < 16; i++) {
            float4 g4 = ge[i];
            s += xv[i].x * g4.x + xv[i].y * g4.y + xv[i].z * g4.z + xv[i].w * g4.w;
        }
        part[(half * 128 + row) * NEXP + e] = s;
    }
    __syncthreads();

    if (half == 0) {
        float lg[NEXP];
        #pragma unroll
        for (int e = 0; e < NEXP; e++)
            lg[e] = part[row * NEXP + e] + part[(128 + row) * NEXP + e] + __ldg(gb + e);
        float m = lg[0];
        #pragma unroll
        for (int e = 1; e < NEXP; e++) m = fmaxf(m, lg[e]);
        float p[NEXP], s = 0.f;
        #pragma unroll
        for (int e = 0; e < NEXP; e++) { p[e] = expf(lg[e] - m); s += p[e]; }
        const float inv = 1.f / s;
        float g[NEXP];
        #pragma unroll
        for (int e = 0; e < NEXP; e++) g[e] = p[e] * inv;

        int i1 = 0;
        #pragma unroll
        for (int e = 1; e < NEXP; e++) if (lg[e] > lg[i1]) i1 = e;
        int i2 = (i1 == 0) ? 1 : 0;
        #pragma unroll
        for (int e = 0; e < NEXP; e++) if (e != i1 && lg[e] > lg[i2]) i2 = e;

        const int a  = min(i1, i2);
        const int bb = max(i1, i2);
        const int pidx = a * 8 + bb;
        const long tok = tok0 + row;

        const int r = atomicAdd(&g_hist[pidx], 1);
        g_pr[tok] = ((uint32_t)pidx << 24) | (uint32_t)r;
        skey[row] = r & 7;                        // swizzle key for this token's row image

        g_rec[2 * tok]     = make_uint4(packh2(g[0], g[1]), packh2(g[2], g[3]),
                                        packh2(g[4], g[5]), packh2(g[6], g[7]));
        g_rec[2 * tok + 1] = make_uint4(__float_as_uint(g[a]), __float_as_uint(g[bb]),
                                        (uint32_t)tok, 0u);
    }
    __syncthreads();

    // write pre-swizzled f16 row image (key = rank&7 == tile-row&7)
    {
        const int key = skey[row];
        unsigned char* dst = g_xh + (size_t)(tok0 + row) * 256;
        #pragma unroll
        for (int j = 0; j < 8; j++) {
            uint4 u = make_uint4(packh2(xv[2*j].x,   xv[2*j].y),
                                 packh2(xv[2*j].z,   xv[2*j].w),
                                 packh2(xv[2*j+1].x, xv[2*j+1].y),
                                 packh2(xv[2*j+1].z, xv[2*j+1].w));
            const int c16 = half * 8 + j;
            *(uint4*)(dst + ((c16 ^ key) << 4)) = u;
        }
    }
}

// ---------------- kernel 3: parallel scan + tile table (padded offsets) ----------------

__global__ void scan_kernel() {
    __shared__ int st[64];
    const int p = threadIdx.x;
    const int c  = g_hist[p];
    const int nt = (c + 127) >> 7;
    st[p] = nt;
    __syncthreads();
    #pragma unroll
    for (int d = 1; d < 64; d <<= 1) {
        int vt = 0;
        if (p >= d) vt = st[p - d];
        __syncthreads();
        st[p] += vt;
        __syncthreads();
    }
    const int tb0  = st[p] - nt;
    const int base = tb0 * 128;
    g_off[p] = base;
    if (p == 63) g_ntiles[0] = st[63];
    const int a = p >> 3, bb = p & 7;
    int tb = tb0;
    for (int s = 0; s < c; s += 128, tb++)
        g_tiles[tb] = make_int4(base + s, min(128, c - s), a, bb);
}

// ---------------- kernel 4: fill grouped token list + grouped records ----------------

__global__ void fill_kernel() {
    const int tok = blockIdx.x * blockDim.x + threadIdx.x;
    const uint32_t v = g_pr[tok];
    const int pos = g_off[v >> 24] + (int)(v & 0xFFFFFF);
    g_tok[pos] = tok;
    g_recg[2 * (size_t)pos]     = g_rec[2 * (size_t)tok];
    g_recg[2 * (size_t)pos + 1] = g_rec[2 * (size_t)tok + 1];
}

// ---------------- kernel 5: persistent pair-group GEMM (tile-major, both N-halves) ----------------

__device__ __forceinline__ void gather_bulk(uint32_t sb, int tid, int tile, int count) {
    if (tid == 0)
        MBARRIER_EXPECT_TX(sb + OFF_MBAR, (uint32_t)count * 256u + 4096u);
    if (tid < 128) {
        if (tid < count) {
            const int tok = __ldg(&g_tok[tile * 128 + tid]);
            CP_BULK(sb + OFF_A + tid * 256,
                    g_xh + (size_t)tok * 256, 256u, sb + OFF_MBAR);
        }
    } else if (tid == 128) {
        CP_BULK(sb + OFF_REC,
                (const char*)&g_recg[2 * (size_t)tile * 128], 4096u, sb + OFF_MBAR);
    }
}

__device__ __forceinline__ void bulk_W(uint32_t sb, int ea, int eb) {
    MBARRIER_EXPECT_TX(sb + OFF_MBAR + 8, W_TX);
    CP_BULK(sb + OFF_W,         g_Wh + (size_t)ea * 32768,         16384u, sb + OFF_MBAR + 8);
    CP_BULK(sb + OFF_W + 16384, g_Wh + (size_t)eb * 32768,         16384u, sb + OFF_MBAR + 8);
    CP_BULK(sb + OFF_W + 32768, g_Wh + (size_t)ea * 32768 + 16384, 16384u, sb + OFF_MBAR + 8);
    CP_BULK(sb + OFF_W + 49152, g_Wh + (size_t)eb * 32768 + 16384, 16384u, sb + OFF_MBAR + 8);
}

__global__ void __launch_bounds__(256, 2)
moe_main_kernel(const float* __restrict__ b,
                float* __restrict__ out)
{
    extern __shared__ char smem[];
    const uint32_t sb = smem_u32(smem);

    const int tid  = threadIdx.x;
    const int lane = tid & 31;
    const int wid  = tid >> 5;

    const int nt = __ldg(g_ntiles);
    const int chunk = (nt + gridDim.x - 1) / gridDim.x;
    const int c0 = blockIdx.x * chunk;
    const int c1 = min(c0 + chunk, nt);
    if (c0 >= c1) return;

    if (tid == 0) {
        MBARRIER_INIT(sb + OFF_MBAR,     1);
        MBARRIER_INIT(sb + OFF_MBAR + 8, 1);
    }
    if (tid < DIM) {
        float bv[NEXP];
        #pragma unroll
        for (int e = 0; e < NEXP; e++) bv[e] = __ldg(b + e * DIM + tid);
        uint32_t* dst = (uint32_t*)(smem + OFF_BG + tid * 16);
        dst[0] = packh2(bv[0], bv[1]);
        dst[1] = packh2(bv[2], bv[3]);
        dst[2] = packh2(bv[4], bv[5]);
        dst[3] = packh2(bv[6], bv[7]);
    }
    __syncthreads();                             // mbarrier init + BG visible

    int4 cur = __ldg(&g_tiles[c0]);
    FENCE_PROXY_ASYNC();
    gather_bulk(sb, tid, c0, cur.y);
    if (tid == 0) bulk_W(sb, cur.z, cur.w);
    int phA = 0, phW = 0;
    bool wpend = true;

    // warp tiling: 4(m) x 2(n); warp tile 32 x 32; dual-expert acc (64 regs)
    const int mgrp = wid >> 1;
    const int ngrp = wid & 1;
    const int arow = lane & 15;
    const int hiA  = lane >> 4;
    const int brow = ((lane >> 4) & 1) * 8 + (lane & 7);
    const int hiB  = (lane >> 3) & 1;
    const int xA   = arow & 7;
    const int xB   = lane & 7;

    for (int i = c0; i < c1; i++) {
        MBARRIER_WAIT_PARITY(sb + OFF_MBAR, phA); phA ^= 1;
        if (wpend) { MBARRIER_WAIT_PARITY(sb + OFF_MBAR + 8, phW); phW ^= 1; wpend = false; }

        const int count = cur.y;
        const uint32_t baseA0 = sb + OFF_A + (mgrp * 32 + arow) * 256;
        const uint32_t baseA1 = baseA0 + 16 * 256;

        #pragma unroll
        for (int nh = 0; nh < 2; nh++) {
            float accA[2][4][4], accB[2][4][4];
            #pragma unroll
            for (int t2 = 0; t2 < 2; t2++)
                #pragma unroll
                for (int u = 0; u < 4; u++)
                    #pragma unroll
                    for (int q = 0; q < 4; q++) { accA[t2][u][q] = 0.f; accB[t2][u][q] = 0.f; }

            const uint32_t basePa = sb + OFF_W + nh * 32768 + (ngrp * 32 + brow) * 256;
            const uint32_t basePb = basePa + 16384;

            #pragma unroll
            for (int ks = 0; ks < 8; ks++) {
                const uint32_t ofA = (uint32_t)(((2 * ks + hiA) ^ xA) << 4);
                const uint32_t ofB = (uint32_t)(((2 * ks + hiB) ^ xB) << 4);
                uint32_t a0[4], a1[4];
                LDSM_X4(a0[0], a0[1], a0[2], a0[3], baseA0 + ofA);
                LDSM_X4(a1[0], a1[1], a1[2], a1[3], baseA1 + ofA);
                #pragma unroll
                for (int u = 0; u < 2; u++) {
                    uint32_t p0, p1, p2, p3;
                    LDSM_X4(p0, p1, p2, p3, basePa + (uint32_t)(u * 16 * 256) + ofB);
                    MMA_16816(accA[0][2*u],   a0[0], a0[1], a0[2], a0[3], p0, p1);
                    MMA_16816(accA[0][2*u+1], a0[0], a0[1], a0[2], a0[3], p2, p3);
                    MMA_16816(accA[1][2*u],   a1[0], a1[1], a1[2], a1[3], p0, p1);
                    MMA_16816(accA[1][2*u+1], a1[0], a1[1], a1[2], a1[3], p2, p3);
                }
                #pragma unroll
                for (int u = 0; u < 2; u++) {
                    uint32_t q0, q1, q2, q3;
                    LDSM_X4(q0, q1, q2, q3, basePb + (uint32_t)(u * 16 * 256) + ofB);
                    MMA_16816(accB[0][2*u],   a0[0], a0[1], a0[2], a0[3], q0, q1);
                    MMA_16816(accB[0][2*u+1], a0[0], a0[1], a0[2], a0[3], q2, q3);
                    MMA_16816(accB[1][2*u],   a1[0], a1[1], a1[2], a1[3], q0, q1);
                    MMA_16816(accB[1][2*u+1], a1[0], a1[1], a1[2], a1[3], q2, q3);
                }
            }

            // combine accA = ga*accA + gb*accB (g12 from records)
            #pragma unroll
            for (int t2 = 0; t2 < 2; t2++) {
                const int rlo = mgrp * 32 + t2 * 16 + (lane >> 2);
                const float2 glo = *(const float2*)(smem + OFF_REC + rlo * 32 + 16);
                const float2 ghi = *(const float2*)(smem + OFF_REC + (rlo + 8) * 32 + 16);
                #pragma unroll
                for (int u = 0; u < 4; u++) {
                    accA[t2][u][0] = glo.x * accA[t2][u][0] + glo.y * accB[t2][u][0];
                    accA[t2][u][1] = glo.x * accA[t2][u][1] + glo.y * accB[t2][u][1];
                    accA[t2][u][2] = ghi.x * accA[t2][u][2] + ghi.y * accB[t2][u][2];
                    accA[t2][u][3] = ghi.x * accA[t2][u][3] + ghi.y * accB[t2][u][3];
                }
            }

            // bias MMA (k8): accA += gates_full @ b^T slice (gates from records, stride 32)
            {
                uint32_t bg[4];
                LDSM_X4(bg[0], bg[1], bg[2], bg[3],
                        sb + OFF_BG + (uint32_t)((nh * 64 + ngrp * 32 + lane) * 16));
                #pragma unroll
                for (int t2 = 0; t2 < 2; t2++) {
                    uint32_t ag0, ag1;
                    LDSM_X2(ag0, ag1,
                            sb + OFF_REC + (uint32_t)((mgrp * 32 + t2 * 16 + (lane & 15)) * 32));
                    #pragma unroll
                    for (int u = 0; u < 4; u++)
                        MMA_16808(accA[t2][u], ag0, ag1, bg[u]);
                }
            }

            // scatter stores (sector-perfect: 4 lanes x 8B = one 32B sector)
            {
                const int colb = nh * 64 + ngrp * 32 + (lane & 3) * 2;
                #pragma unroll
                for (int t2 = 0; t2 < 2; t2++) {
                    const int lr = mgrp * 32 + t2 * 16 + (lane >> 2);
                    const bool ok0 = lr < count;
                    const bool ok1 = (lr + 8) < count;
                    const long tk0 = ok0 ? *(const int*)(smem + OFF_REC + lr * 32 + 24) : 0;
                    const long tk1 = ok1 ? *(const int*)(smem + OFF_REC + (lr + 8) * 32 + 24) : 0;
                    #pragma unroll
                    for (int u = 0; u < 4; u++) {
                        const int col = colb + u * 8;
                        if (ok0) *(float2*)(out + tk0 * DIM + col) =
                            make_float2(accA[t2][u][0], accA[t2][u][1]);
                        if (ok1) *(float2*)(out + tk1 * DIM + col) =
                            make_float2(accA[t2][u][2], accA[t2][u][3]);
                    }
                }
            }
        }

        __syncthreads();     // all reads of A/REC/W for this tile done

        if (i + 1 < c1) {
            int4 nxt = __ldg(&g_tiles[i + 1]);
            FENCE_PROXY_ASYNC();
            gather_bulk(sb, tid, i + 1, nxt.y);
            if (nxt.z != cur.z || nxt.w != cur.w) {
                if (tid == 0) bulk_W(sb, nxt.z, nxt.w);
                wpend = true;
            }
            cur = nxt;
        }
    }
}

// ---------------- launch ----------------

extern "C" void kernel_launch(void* const* d_in, const int* in_sizes, int n_in,
                              void* d_out, int out_size)
{
    const float* x  = (const float*)d_in[0];
    const float* gW = (const float*)d_in[1];
    const float* gb = (const float*)d_in[2];
    const float* W  = (const float*)d_in[3];
    const float* b  = (const float*)d_in[4];
    float* out = (float*)d_out;

    int sms = 148;
    cudaDeviceGetAttribute(&sms, cudaDevAttrMultiProcessorCount, 0);

    convert_w_kernel<<<64, 256>>>(W);
    routing_kernel<<<NTOK / 128, 256>>>(x, gW, gb);
    scan_kernel<<<1, 64>>>();
    fill_kernel<<<NTOK / 256, 256>>>();

    cudaFuncSetAttribute(moe_main_kernel,
                         cudaFuncAttributeMaxDynamicSharedMemorySize, SMEM_MAIN);
    moe_main_kernel<<<sms * 2, 256, SMEM_MAIN>>>(b, out);
}

// round 17
// speedup vs baseline: 1.0311x; 1.0311x over previous
#include <cuda_runtime.h>
#include <cuda_fp16.h>
#include <cstdint>

// ---------------- PTX helpers (family-level: sm_80/sm_90 non-'a') ----------------

__device__ __forceinline__ uint32_t smem_u32(const void* p) {
    uint32_t a;
    asm("{ .reg .u64 t; cvta.to.shared.u64 t, %1; cvt.u32.u64 %0, t; }" : "=r"(a) : "l"(p));
    return a;
}

#define LDSM_X4(r0,r1,r2,r3,addr) \
    asm volatile("ldmatrix.sync.aligned.m8n8.x4.shared.b16 {%0,%1,%2,%3}, [%4];" \
        : "=r"(r0),"=r"(r1),"=r"(r2),"=r"(r3) : "r"(addr))
#define LDSM_X2(r0,r1,addr) \
    asm volatile("ldmatrix.sync.aligned.m8n8.x2.shared.b16 {%0,%1}, [%2];" \
        : "=r"(r0),"=r"(r1) : "r"(addr))

#define MMA_16816(c,a0,a1,a2,a3,b0,b1) \
    asm volatile("mma.sync.aligned.m16n8k16.row.col.f32.f16.f16.f32 " \
        "{%0,%1,%2,%3}, {%4,%5,%6,%7}, {%8,%9}, {%0,%1,%2,%3};" \
        : "+f"((c)[0]),"+f"((c)[1]),"+f"((c)[2]),"+f"((c)[3]) \
        : "r"(a0),"r"(a1),"r"(a2),"r"(a3),"r"(b0),"r"(b1))
#define MMA_16808(c,a0,a1,b0) \
    asm volatile("mma.sync.aligned.m16n8k8.row.col.f32.f16.f16.f32 " \
        "{%0,%1,%2,%3}, {%4,%5}, {%6}, {%0,%1,%2,%3};" \
        : "+f"((c)[0]),"+f"((c)[1]),"+f"((c)[2]),"+f"((c)[3]) \
        : "r"(a0),"r"(a1),"r"(b0))

// bulk copy (UBLKCP, validated on compute_103) + mbarrier
#define CP_BULK(dst,src,size,mbar) \
    asm volatile("cp.async.bulk.shared::cluster.global.mbarrier::complete_tx::bytes " \
        "[%0], [%1], %2, [%3];" :: "r"(dst),"l"(src),"r"(size),"r"(mbar) : "memory")
#define MBARRIER_INIT(mbar, cnt) \
    asm volatile("mbarrier.init.shared.b64 [%0], %1;" :: "r"((uint32_t)(mbar)), "r"((uint32_t)(cnt)) : "memory")
#define MBARRIER_EXPECT_TX(mbar, tx) \
    asm volatile("mbarrier.arrive.expect_tx.shared.b64 _, [%0], %1;" :: "r"((uint32_t)(mbar)), "r"((uint32_t)(tx)) : "memory")
#define FENCE_PROXY_ASYNC() asm volatile("fence.proxy.async.shared::cta;" ::: "memory")

#define MBARRIER_WAIT_PARITY(mbar_smem_addr, phase_parity) do { \
    uint32_t _mbar = (uint32_t)(mbar_smem_addr); \
    uint32_t _parity = (uint32_t)(phase_parity); \
    uint32_t _done; \
    asm volatile( \
        "{\n\t.reg .pred p;\n\t" \
        "mbarrier.try_wait.parity.acquire.cta.shared::cta.b64 p, [%1], %2;\n\t" \
        "selp.b32 %0, 1, 0, p;\n\t}" \
        : "=r"(_done) : "r"(_mbar), "r"(_parity) : "memory"); \
    if (!_done) { \
        asm volatile( \
            "{\n\t.reg .pred P1;\n\t" \
            "WAIT_LOOP_%=:\n\t" \
            "mbarrier.try_wait.parity.acquire.cta.shared::cta.b64 P1, [%0], %1, 0x989680;\n\t" \
            "@P1 bra.uni WAIT_DONE_%=;\n\t" \
            "bra.uni WAIT_LOOP_%=;\n\t" \
            "WAIT_DONE_%=:\n\t}" \
            :: "r"(_mbar), "r"(_parity) : "memory"); \
    } \
} while(0)

__device__ __forceinline__ uint32_t packh2(float a, float b) {
    return (uint32_t)__half_as_ushort(__float2half_rn(a)) |
           ((uint32_t)__half_as_ushort(__float2half_rn(b)) << 16);
}

// ---------------- problem constants ----------------

static constexpr int DIM   = 128;
static constexpr int NEXP  = 8;
static constexpr int NTOK  = 524288;
static constexpr int MAX_TILES = 4160;
static constexpr int NPOS  = MAX_TILES * 128;

// main-kernel smem layout (bytes) — per CTA (2 CTAs/SM)
static constexpr int OFF_A    = 0;        // 2 x 32768  (x f16 tile images, pre-swizzled)
static constexpr int OFF_REC  = 65536;    // 2 x 4096   (per-row records: gf16B, ga, gb, tok, pad)
static constexpr int OFF_W    = 73728;    // 32768      (Wa-half 16KB + Wb-half 16KB)
static constexpr int OFF_BG   = 106496;   // 2048       (b^T f16 [128][16B], all cols)
static constexpr int OFF_MBAR = 108544;   // 3 x 8      (abar0, abar1, wbar)
static constexpr int SMEM_MAIN = 108576;  // ~106 KB -> 2 CTAs/SM

static constexpr uint32_t W_TX = 32768u;

// ---------------- device scratch (static: no allocations) ----------------

__device__ __align__(16) unsigned char g_Wh[NEXP * 32768];       // [e][nh 16KB x2] images
__device__ __align__(16) unsigned char g_xh[(size_t)NTOK * 256]; // x f16, token order, PRE-SWIZZLED by rank&7
__device__ __align__(16) uint4 g_rec[(size_t)NTOK * 2];          // [tok]: {gf(16B)},{ga,gb,tok,0}
__device__ __align__(16) uint4 g_recg[(size_t)NPOS * 2];         // records in grouped (padded) order
__device__ int    g_hist[64];
__device__ int    g_off[64];                 // padded group base (multiple of 128)
__device__ int    g_ntiles[1];
__device__ int4   g_tiles[MAX_TILES];        // (start=tile*128, count, e_a, e_b)
__device__ uint32_t g_pr[NTOK];              // pair<<24 | rank
__device__ __align__(16) int g_tok[NPOS];    // grouped token ids (padded slots unused)

// ---------------- kernel 1: W fp32 -> f16 half-expert tile images ----------------

__global__ void convert_w_kernel(const float* __restrict__ W) {
    if (blockIdx.x == 0 && threadIdx.x < 64) g_hist[threadIdx.x] = 0;
    const int i = blockIdx.x * blockDim.x + threadIdx.x;   // 16384 16B-chunks
    const int e   = i >> 11;
    const int f   = (i >> 4) & 127;       // output feature row
    const int c16 = i & 15;
    const float4* src = (const float4*)(W + ((size_t)e * 128 + f) * 128 + c16 * 8);
    float4 v0 = src[0], v1 = src[1];
    uint4 u = make_uint4(packh2(v0.x, v0.y), packh2(v0.z, v0.w),
                         packh2(v1.x, v1.y), packh2(v1.z, v1.w));
    *(uint4*)(g_Wh + e * 32768 + (f >> 6) * 16384 + (f & 63) * 256
              + ((c16 ^ (f & 7)) << 4)) = u;
}

// ---------------- kernel 2: routing (gating + top-2 + pre-swizzled x->f16, coalesced) ----------------

__global__ void __launch_bounds__(256, 2)
routing_kernel(const float* __restrict__ x,
               const float* __restrict__ gW,
               const float* __restrict__ gb)
{
    __shared__ float gws[NEXP * DIM];          // 4 KB
    __shared__ float part[256 * NEXP];         // 8 KB
    __shared__ int   skey[128];
    __shared__ char  xstage[128 * 256];        // 32 KB (pre-swizzled row images)

    const int tid  = threadIdx.x;
    const int row  = tid & 127;
    const int half = tid >> 7;
    const long tok0 = (long)blockIdx.x * 128;

    ((float4*)gws)[tid] = ((const float4*)gW)[tid];

    float4 xv[16];
    {
        const float4* xg = (const float4*)(x + (tok0 + row) * DIM + half * 64);
        #pragma unroll
        for (int i = 0; i < 16; i++) xv[i] = __ldg(xg + i);
    }
    __syncthreads();

    #pragma unroll
    for (int e = 0; e < NEXP; e++) {
        const float4* ge = (const float4*)(gws + e * DIM) + half * 16;
        float s = 0.f;
        #pragma unroll
        for (int i = 0; i < 16; i++) {
            float4 g4 = ge[i];
            s += xv[i].x * g4.x + xv[i].y * g4.y + xv[i].z * g4.z + xv[i].w * g4.w;
        }
        part[(half * 128 + row) * NEXP + e] = s;
    }
    __syncthreads();

    if (half == 0) {
        float lg[NEXP];
        #pragma unroll
        for (int e = 0; e < NEXP; e++)
            lg[e] = part[row * NEXP + e] + part[(128 + row) * NEXP + e] + __ldg(gb + e);
        float m = lg[0];
        #pragma unroll
        for (int e = 1; e < NEXP; e++) m = fmaxf(m, lg[e]);
        float p[NEXP], s = 0.f;
        #pragma unroll
        for (int e = 0; e < NEXP; e++) { p[e] = expf(lg[e] - m); s += p[e]; }
        const float inv = 1.f / s;
        float g[NEXP];
        #pragma unroll
        for (int e = 0; e < NEXP; e++) g[e] = p[e] * inv;

        int i1 = 0;
        #pragma unroll
        for (int e = 1; e < NEXP; e++) if (lg[e] > lg[i1]) i1 = e;
        int i2 = (i1 == 0) ? 1 : 0;
        #pragma unroll
        for (int e = 0; e < NEXP; e++) if (e != i1 && lg[e] > lg[i2]) i2 = e;

        const int a  = min(i1, i2);
        const int bb = max(i1, i2);
        const int pidx = a * 8 + bb;
        const long tok = tok0 + row;

        const int r = atomicAdd(&g_hist[pidx], 1);
        g_pr[tok] = ((uint32_t)pidx << 24) | (uint32_t)r;
        skey[row] = r & 7;                        // swizzle key for this token's row image

        g_rec[2 * tok]     = make_uint4(packh2(g[0], g[1]), packh2(g[2], g[3]),
                                        packh2(g[4], g[5]), packh2(g[6], g[7]));
        g_rec[2 * tok + 1] = make_uint4(__float_as_uint(g[a]), __float_as_uint(g[bb]),
                                        (uint32_t)tok, 0u);
    }
    __syncthreads();

    // stage pre-swizzled f16 row image in smem (key = rank&7 == tile-row&7)
    {
        const int key = skey[row];
        char* dst = xstage + row * 256;
        #pragma unroll
        for (int j = 0; j < 8; j++) {
            uint4 u = make_uint4(packh2(xv[2*j].x,   xv[2*j].y),
                                 packh2(xv[2*j].z,   xv[2*j].w),
                                 packh2(xv[2*j+1].x, xv[2*j+1].y),
                                 packh2(xv[2*j+1].z, xv[2*j+1].w));
            const int c16 = half * 8 + j;
            *(uint4*)(dst + ((c16 ^ key) << 4)) = u;
        }
    }
    __syncthreads();

    // coalesced store to g_xh (full 32B sectors; swizzle preserved, row-internal)
    {
        uint4* xg = (uint4*)(g_xh + (size_t)tok0 * 256);
        const uint4* xs = (const uint4*)xstage;
        #pragma unroll
        for (int it = 0; it < 8; it++) {
            const int j = tid + it * 256;          // 2048 16B chunks, linear
            xg[j] = xs[j];
        }
    }
}

// ---------------- kernel 3: parallel scan + tile table (padded offsets) ----------------

__global__ void scan_kernel() {
    __shared__ int st[64];
    const int p = threadIdx.x;
    const int c  = g_hist[p];
    const int nt = (c + 127) >> 7;
    st[p] = nt;
    __syncthreads();
    #pragma unroll
    for (int d = 1; d < 64; d <<= 1) {
        int vt = 0;
        if (p >= d) vt = st[p - d];
        __syncthreads();
        st[p] += vt;
        __syncthreads();
    }
    const int tb0  = st[p] - nt;
    const int base = tb0 * 128;
    g_off[p] = base;
    if (p == 63) g_ntiles[0] = st[63];
    const int a = p >> 3, bb = p & 7;
    int tb = tb0;
    for (int s = 0; s < c; s += 128, tb++)
        g_tiles[tb] = make_int4(base + s, min(128, c - s), a, bb);
}

// ---------------- kernel 4: fill grouped token list + grouped records ----------------

__global__ void fill_kernel() {
    const int tok = blockIdx.x * blockDim.x + threadIdx.x;
    const uint32_t v = g_pr[tok];
    const int pos = g_off[v >> 24] + (int)(v & 0xFFFFFF);
    g_tok[pos] = tok;
    g_recg[2 * (size_t)pos]     = g_rec[2 * (size_t)tok];
    g_recg[2 * (size_t)pos + 1] = g_rec[2 * (size_t)tok + 1];
}

// ---------------- kernel 5: persistent pair-group GEMM (row bulks + 1 rec bulk) ----------------

__device__ __forceinline__ void gather_bulk(uint32_t sb, int tid, int tile, int q, int count) {
    if (tid == 0)
        MBARRIER_EXPECT_TX(sb + OFF_MBAR + q * 8, (uint32_t)count * 256u + 4096u);
    if (tid < 128) {
        if (tid < count) {
            const int tok = __ldg(&g_tok[tile * 128 + tid]);
            CP_BULK(sb + OFF_A + q * 32768 + tid * 256,
                    g_xh + (size_t)tok * 256, 256u, sb + OFF_MBAR + q * 8);
        }
    } else if (tid == 128) {
        CP_BULK(sb + OFF_REC + q * 4096,
                (const char*)&g_recg[2 * (size_t)tile * 128], 4096u, sb + OFF_MBAR + q * 8);
    }
}

__device__ __forceinline__ void bulk_W(uint32_t sb, int ea, int eb, int nh) {
    MBARRIER_EXPECT_TX(sb + OFF_MBAR + 16, W_TX);
    CP_BULK(sb + OFF_W,         g_Wh + (size_t)ea * 32768 + nh * 16384, 16384u, sb + OFF_MBAR + 16);
    CP_BULK(sb + OFF_W + 16384, g_Wh + (size_t)eb * 32768 + nh * 16384, 16384u, sb + OFF_MBAR + 16);
}

__global__ void __launch_bounds__(256, 2)
moe_main_kernel(const float* __restrict__ b,
                float* __restrict__ out)
{
    extern __shared__ char smem[];
    const uint32_t sb = smem_u32(smem);

    const int tid  = threadIdx.x;
    const int lane = tid & 31;
    const int wid  = tid >> 5;

    const int nt = __ldg(g_ntiles);
    const int njobs = nt * 2;                    // jobs [0,nt): nh=0; [nt,2nt): nh=1
    const int chunk = (njobs + gridDim.x - 1) / gridDim.x;
    const int c0 = blockIdx.x * chunk;
    const int c1 = min(c0 + chunk, njobs);
    if (c0 >= c1) return;

    if (tid == 0) {
        MBARRIER_INIT(sb + OFF_MBAR,      1);
        MBARRIER_INIT(sb + OFF_MBAR + 8,  1);
        MBARRIER_INIT(sb + OFF_MBAR + 16, 1);
    }
    if (tid < DIM) {
        float bv[NEXP];
        #pragma unroll
        for (int e = 0; e < NEXP; e++) bv[e] = __ldg(b + e * DIM + tid);
        uint32_t* dst = (uint32_t*)(smem + OFF_BG + tid * 16);
        dst[0] = packh2(bv[0], bv[1]);
        dst[1] = packh2(bv[2], bv[3]);
        dst[2] = packh2(bv[4], bv[5]);
        dst[3] = packh2(bv[6], bv[7]);
    }
    __syncthreads();                             // mbarrier init + BG visible

    int curNh   = (c0 >= nt) ? 1 : 0;
    int4 cur    = __ldg(&g_tiles[(c0 >= nt) ? c0 - nt : c0]);

    FENCE_PROXY_ASYNC();
    gather_bulk(sb, tid, (c0 >= nt) ? c0 - nt : c0, 0, cur.y);
    if (tid == 0) bulk_W(sb, cur.z, cur.w, curNh);
    int phA0 = 0, phA1 = 0, phW = 0;
    bool wpend = true;

    // warp tiling: 4(m) x 2(n); warp tile 32 x 32; dual-expert acc (64 regs)
    const int mgrp = wid >> 1;
    const int ngrp = wid & 1;
    const int arow = lane & 15;
    const int hiA  = lane >> 4;
    const int brow = ((lane >> 4) & 1) * 8 + (lane & 7);
    const int hiB  = (lane >> 3) & 1;
    const int xA   = arow & 7;
    const int xB   = lane & 7;

    for (int j = c0; j < c1; j++) {
        const int pp = (j - c0) & 1;
        int4 nxt = make_int4(0, 0, cur.z, cur.w);
        int nxtNh = curNh;
        if (j + 1 < c1) {
            const int jn = j + 1;
            nxtNh = (jn >= nt) ? 1 : 0;
            nxt = __ldg(&g_tiles[(jn >= nt) ? jn - nt : jn]);
            FENCE_PROXY_ASYNC();
            gather_bulk(sb, tid, (jn >= nt) ? jn - nt : jn, pp ^ 1, nxt.y);
        }

        if (pp == 0) { MBARRIER_WAIT_PARITY(sb + OFF_MBAR,     phA0); phA0 ^= 1; }
        else         { MBARRIER_WAIT_PARITY(sb + OFF_MBAR + 8, phA1); phA1 ^= 1; }
        if (wpend)   { MBARRIER_WAIT_PARITY(sb + OFF_MBAR + 16, phW); phW ^= 1; wpend = false; }

        const int count = cur.y;
        const uint32_t recb = sb + OFF_REC + pp * 4096;

        float accA[2][4][4], accB[2][4][4];
        #pragma unroll
        for (int t2 = 0; t2 < 2; t2++)
            #pragma unroll
            for (int u = 0; u < 4; u++)
                #pragma unroll
                for (int q = 0; q < 4; q++) { accA[t2][u][q] = 0.f; accB[t2][u][q] = 0.f; }

        const uint32_t baseA0 = sb + OFF_A + pp * 32768 + (mgrp * 32 + arow) * 256;
        const uint32_t baseA1 = baseA0 + 16 * 256;
        const uint32_t basePa = sb + OFF_W + (ngrp * 32 + brow) * 256;
        const uint32_t basePb = basePa + 16384;

        #pragma unroll
        for (int ks = 0; ks < 8; ks++) {
            const uint32_t ofA = (uint32_t)(((2 * ks + hiA) ^ xA) << 4);
            const uint32_t ofB = (uint32_t)(((2 * ks + hiB) ^ xB) << 4);
            uint32_t a0[4], a1[4];
            LDSM_X4(a0[0], a0[1], a0[2], a0[3], baseA0 + ofA);
            LDSM_X4(a1[0], a1[1], a1[2], a1[3], baseA1 + ofA);
            #pragma unroll
            for (int u = 0; u < 2; u++) {
                uint32_t p0, p1, p2, p3;
                LDSM_X4(p0, p1, p2, p3, basePa + (uint32_t)(u * 16 * 256) + ofB);
                MMA_16816(accA[0][2*u],   a0[0], a0[1], a0[2], a0[3], p0, p1);
                MMA_16816(accA[0][2*u+1], a0[0], a0[1], a0[2], a0[3], p2, p3);
                MMA_16816(accA[1][2*u],   a1[0], a1[1], a1[2], a1[3], p0, p1);
                MMA_16816(accA[1][2*u+1], a1[0], a1[1], a1[2], a1[3], p2, p3);
            }
            #pragma unroll
            for (int u = 0; u < 2; u++) {
                uint32_t q0, q1, q2, q3;
                LDSM_X4(q0, q1, q2, q3, basePb + (uint32_t)(u * 16 * 256) + ofB);
                MMA_16816(accB[0][2*u],   a0[0], a0[1], a0[2], a0[3], q0, q1);
                MMA_16816(accB[0][2*u+1], a0[0], a0[1], a0[2], a0[3], q2, q3);
                MMA_16816(accB[1][2*u],   a1[0], a1[1], a1[2], a1[3], q0, q1);
                MMA_16816(accB[1][2*u+1], a1[0], a1[1], a1[2], a1[3], q2, q3);
            }
        }

        // combine accA = ga*accA + gb*accB (g12 from records)
        #pragma unroll
        for (int t2 = 0; t2 < 2; t2++) {
            const int rlo = mgrp * 32 + t2 * 16 + (lane >> 2);
            const float2 glo = *(const float2*)(smem + (recb - sb) + rlo * 32 + 16);
            const float2 ghi = *(const float2*)(smem + (recb - sb) + (rlo + 8) * 32 + 16);
            #pragma unroll
            for (int u = 0; u < 4; u++) {
                accA[t2][u][0] = glo.x * accA[t2][u][0] + glo.y * accB[t2][u][0];
                accA[t2][u][1] = glo.x * accA[t2][u][1] + glo.y * accB[t2][u][1];
                accA[t2][u][2] = ghi.x * accA[t2][u][2] + ghi.y * accB[t2][u][2];
                accA[t2][u][3] = ghi.x * accA[t2][u][3] + ghi.y * accB[t2][u][3];
            }
        }

        // bias MMA (k8): accA += gates_full @ b^T slice (gates from records, stride 32)
        {
            uint32_t bg[4];
            LDSM_X4(bg[0], bg[1], bg[2], bg[3],
                    sb + OFF_BG + (uint32_t)((curNh * 64 + ngrp * 32 + lane) * 16));
            #pragma unroll
            for (int t2 = 0; t2 < 2; t2++) {
                uint32_t ag0, ag1;
                LDSM_X2(ag0, ag1,
                        recb + (uint32_t)((mgrp * 32 + t2 * 16 + (lane & 15)) * 32));
                #pragma unroll
                for (int u = 0; u < 4; u++)
                    MMA_16808(accA[t2][u], ag0, ag1, bg[u]);
            }
        }

        // scatter stores (sector-perfect: 4 lanes x 8B = one 32B sector)
        {
            const int colb = curNh * 64 + ngrp * 32 + (lane & 3) * 2;
            #pragma unroll
            for (int t2 = 0; t2 < 2; t2++) {
                const int lr = mgrp * 32 + t2 * 16 + (lane >> 2);
                const bool ok0 = lr < count;
                const bool ok1 = (lr + 8) < count;
                const long tk0 = ok0 ? *(const int*)(smem + (recb - sb) + lr * 32 + 24) : 0;
                const long tk1 = ok1 ? *(const int*)(smem + (recb - sb) + (lr + 8) * 32 + 24) : 0;
                #pragma unroll
                for (int u = 0; u < 4; u++) {
                    const int col = colb + u * 8;
                    if (ok0) *(float2*)(out + tk0 * DIM + col) =
                        make_float2(accA[t2][u][0], accA[t2][u][1]);
                    if (ok1) *(float2*)(out + tk1 * DIM + col) =
                        make_float2(accA[t2][u][2], accA[t2][u][3]);
                }
            }
        }

        __syncthreads();     // all reads of this job's buffers + W done

        if (j + 1 < c1 && (nxt.z != cur.z || nxt.w != cur.w || nxtNh != curNh)) {
            FENCE_PROXY_ASYNC();
            if (tid == 0) bulk_W(sb, nxt.z, nxt.w, nxtNh);
            wpend = true;
        }
        cur = nxt;
        curNh = nxtNh;
    }
}

// ---------------- launch ----------------

extern "C" void kernel_launch(void* const* d_in, const int* in_sizes, int n_in,
                              void* d_out, int out_size)
{
    const float* x  = (const float*)d_in[0];
    const float* gW = (const float*)d_in[1];
    const float* gb = (const float*)d_in[2];
    const float* W  = (const float*)d_in[3];
    const float* b  = (const float*)d_in[4];
    float* out = (float*)d_out;

    int sms = 148;
    cudaDeviceGetAttribute(&sms, cudaDevAttrMultiProcessorCount, 0);

    convert_w_kernel<<<64, 256>>>(W);
    routing_kernel<<<NTOK / 128, 256>>>(x, gW, gb);
    scan_kernel<<<1, 64>>>();
    fill_kernel<<<NTOK / 256, 256>>>();

    cudaFuncSetAttribute(moe_main_kernel,
                         cudaFuncAttributeMaxDynamicSharedMemorySize, SMEM_MAIN);
    moe_main_kernel<<<sms * 2, 256, SMEM_MAIN>>>(b, out);
}